// round 11
// baseline (speedup 1.0000x reference)
#include <cuda_runtime.h>
#include <cuda_bf16.h>
#include <cstdint>

// ---------------------------------------------------------------------------
// PhimoeSparseMoeBlock: top-2 MoE with SwiGLU experts.
//   H=4096, F=6400, E=8, K=2, T=512.
// GEMMs on the tensor pipe via mma.sync (HMMA) bf16 with a 3-term fp32->bf16
// split:  D = Ahi*Bhi + Alo*Bhi + Ahi*Blo   (fp32 accum).
// R11: CTA 128Mx64N with 128 threads / 4 warps, warp tile 32x64 (R8's proven
// 128 B/MMA smem ratio) + 96.6KB smem => 2 CTAs/SM (R10's occupancy).
// Combines R8 traffic ratio with R10 overlap.
// ---------------------------------------------------------------------------

#define NUM_E   8
#define TOKENS  512
#define HDIM    4096
#define FDIM    6400

// ---- scratch (device globals; no runtime allocation allowed) ----
__device__ int   g_counts[NUM_E];
__device__ int   g_tok [NUM_E * TOKENS];
__device__ int   g_slot[TOKENS * 2];
__device__ float g_wtok[TOKENS * 2];
__device__ float g_h1  [NUM_E * TOKENS * FDIM];           // 104.9 MB f32
__device__ float g_eout[NUM_E * TOKENS * HDIM];           //  67.1 MB f32
__device__ __nv_bfloat16 g_xhi  [TOKENS * HDIM];          // pre-split x
__device__ __nv_bfloat16 g_xlo  [TOKENS * HDIM];
__device__ __nv_bfloat16 g_acthi[NUM_E * TOKENS * FDIM];  // split act (52.4 MB)
__device__ __nv_bfloat16 g_actlo[NUM_E * TOKENS * FDIM];

// =========================== helpers =======================================
__device__ __forceinline__ uint32_t smem_u32(const void* p) {
    uint32_t a;
    asm("{ .reg .u64 t; cvta.to.shared.u64 t, %1; cvt.u32.u64 %0, t; }"
        : "=r"(a) : "l"(p));
    return a;
}
__device__ __forceinline__ uint32_t swz(uint32_t o) { return o ^ ((o >> 3) & 0x70); }

__device__ __forceinline__ uint32_t pack_bf2(__nv_bfloat16 a, __nv_bfloat16 b) {
    return ((uint32_t)__bfloat16_as_ushort(b) << 16) | (uint32_t)__bfloat16_as_ushort(a);
}

__device__ __forceinline__ void ldsm4(uint32_t* r, uint32_t addr) {
    asm volatile("ldmatrix.sync.aligned.m8n8.x4.shared.b16 {%0,%1,%2,%3}, [%4];"
                 : "=r"(r[0]), "=r"(r[1]), "=r"(r[2]), "=r"(r[3]) : "r"(addr));
}
__device__ __forceinline__ void mma16816(float* c, const uint32_t* a, const uint32_t* b) {
    asm volatile(
        "mma.sync.aligned.m16n8k16.row.col.f32.bf16.bf16.f32 "
        "{%0,%1,%2,%3}, {%4,%5,%6,%7}, {%8,%9}, {%0,%1,%2,%3};"
        : "+f"(c[0]), "+f"(c[1]), "+f"(c[2]), "+f"(c[3])
        : "r"(a[0]), "r"(a[1]), "r"(a[2]), "r"(a[3]), "r"(b[0]), "r"(b[1]));
}
__device__ __forceinline__ void cp_async8(uint32_t dst, const void* src) {
    asm volatile("cp.async.ca.shared.global [%0], [%1], 8;" :: "r"(dst), "l"(src));
}
__device__ __forceinline__ void cp_commit() {
    asm volatile("cp.async.commit_group;" ::: "memory");
}
__device__ __forceinline__ void cp_wait0() {
    asm volatile("cp.async.wait_group 0;" ::: "memory");
}

// ========================= router / combine / split ========================
__global__ void zero_counts_kernel() {
    if (threadIdx.x < NUM_E) g_counts[threadIdx.x] = 0;
}

__global__ void router_kernel(const float* __restrict__ x,
                              const float* __restrict__ gw) {
    const int t    = blockIdx.x;
    const int e    = threadIdx.x >> 5;
    const int lane = threadIdx.x & 31;

    const float* xr = x  + (size_t)t * HDIM;
    const float* gr = gw + (size_t)e * HDIM;

    float s = 0.f;
    for (int h = lane * 4; h < HDIM; h += 128) {
        float4 xv = *reinterpret_cast<const float4*>(xr + h);
        float4 gv = *reinterpret_cast<const float4*>(gr + h);
        s += xv.x * gv.x + xv.y * gv.y + xv.z * gv.z + xv.w * gv.w;
    }
    #pragma unroll
    for (int off = 16; off; off >>= 1) s += __shfl_xor_sync(0xffffffffu, s, off);

    __shared__ float logits[NUM_E];
    if (lane == 0) logits[e] = s;
    __syncthreads();

    if (threadIdx.x == 0) {
        float mx = logits[0];
        #pragma unroll
        for (int i = 1; i < NUM_E; ++i) mx = fmaxf(mx, logits[i]);
        float p[NUM_E]; float sum = 0.f;
        #pragma unroll
        for (int i = 0; i < NUM_E; ++i) { p[i] = expf(logits[i] - mx); sum += p[i]; }
        #pragma unroll
        for (int i = 0; i < NUM_E; ++i) p[i] /= sum;

        int i0 = 0;
        #pragma unroll
        for (int i = 1; i < NUM_E; ++i) if (p[i] > p[i0]) i0 = i;
        int i1 = (i0 == 0) ? 1 : 0;
        #pragma unroll
        for (int i = 0; i < NUM_E; ++i) if (i != i0 && p[i] > p[i1]) i1 = i;

        float denom = p[i0] + p[i1];
        int pos0 = atomicAdd(&g_counts[i0], 1);
        g_tok[i0 * TOKENS + pos0] = t;
        g_slot[t * 2 + 0] = i0 * TOKENS + pos0;
        g_wtok[t * 2 + 0] = p[i0] / denom;

        int pos1 = atomicAdd(&g_counts[i1], 1);
        g_tok[i1 * TOKENS + pos1] = t;
        g_slot[t * 2 + 1] = i1 * TOKENS + pos1;
        g_wtok[t * 2 + 1] = p[i1] / denom;
    }
}

__global__ void xsplit_kernel(const float* __restrict__ x) {
    int i = blockIdx.x * blockDim.x + threadIdx.x;
    if (i >= TOKENS * HDIM) return;
    float v = x[i];
    __nv_bfloat16 h = __float2bfloat16(v);
    g_xhi[i] = h;
    g_xlo[i] = __float2bfloat16(v - __bfloat162float(h));
}

__global__ void combine_kernel(float* __restrict__ y) {
    int idx = blockIdx.x * blockDim.x + threadIdx.x;
    if (idx >= TOKENS * HDIM) return;
    int t = idx >> 12;
    int h = idx & (HDIM - 1);
    int   s0 = g_slot[t * 2 + 0], s1 = g_slot[t * 2 + 1];
    float w0 = g_wtok[t * 2 + 0], w1 = g_wtok[t * 2 + 1];
    y[idx] = w0 * g_eout[(size_t)s0 * HDIM + h] + w1 * g_eout[(size_t)s1 * HDIM + h];
}

// =========================== HMMA GEMM =====================================
// CTA tile 128(M) x 64(N), K-chunk 64, 128 threads (4 warps, warp tile 32x64).
// smem double-buffered: [Ahi 16K | Alo 16K | Bhi 8K | Blo 8K] x2 = 96.5 KB
// => 2 CTAs/SM. mma.m16n8k16 x 3 terms, term-outer ordering.
#define T_AHI 0
#define T_ALO 16384
#define T_BHI 32768
#define T_BLO 40960
#define BUF_SZ 49152
#define SMEM_BYTES (2 * BUF_SZ + 512)

__device__ __forceinline__ void split_store(char* hi, char* lo, uint32_t off, float4 v) {
    __nv_bfloat16 h0 = __float2bfloat16(v.x), h1 = __float2bfloat16(v.y),
                  h2 = __float2bfloat16(v.z), h3 = __float2bfloat16(v.w);
    __nv_bfloat16 l0 = __float2bfloat16(v.x - __bfloat162float(h0));
    __nv_bfloat16 l1 = __float2bfloat16(v.y - __bfloat162float(h1));
    __nv_bfloat16 l2 = __float2bfloat16(v.z - __bfloat162float(h2));
    __nv_bfloat16 l3 = __float2bfloat16(v.w - __bfloat162float(h3));
    *reinterpret_cast<uint2*>(hi + off) = make_uint2(pack_bf2(h0, h1), pack_bf2(h2, h3));
    *reinterpret_cast<uint2*>(lo + off) = make_uint2(pack_bf2(l0, l1), pack_bf2(l2, l3));
}

// A (pre-split bf16): 128 gathered rows x 64 cols -> smem via cp.async.
// 128 threads: each handles 16 rows (one 8B segment per row).
__device__ __forceinline__ void load_a_cp(
    const __nv_bfloat16* __restrict__ hs, const __nv_bfloat16* __restrict__ ls,
    const int* __restrict__ s_row, int ld, int kbase,
    uint32_t hi, uint32_t lo, int tid)
{
    const int r0 = tid >> 4;            // 0..7
    const int c  = tid & 15;            // 8-byte (4 bf16) segment
    #pragma unroll
    for (int i = 0; i < 16; ++i) {
        int r = r0 + (i << 3);
        size_t off = (size_t)s_row[r] * ld + kbase + c * 4;
        uint32_t d = swz((uint32_t)(r * 128 + c * 8));
        cp_async8(hi + d, hs + off);
        cp_async8(lo + d, ls + off);
    }
}

// B (fp32 weights, 64 rows x 64 cols per chunk): LDG early into regs ...
// 128 threads: 2 threads per row, 8 float4 each.
__device__ __forceinline__ void ldg_b(const float* __restrict__ base, int ld,
                                      int kbase, int tid, float4* v) {
    const int r  = tid >> 1;            // 0..63
    const int s0 = (tid & 1) << 3;      // float4 segment base: 0 or 8
    #pragma unroll
    for (int i = 0; i < 8; ++i)
        v[i] = *reinterpret_cast<const float4*>(base + (size_t)r * ld + kbase + (s0 + i) * 4);
}
// ... convert+store late (after the MMA block has covered the latency)
__device__ __forceinline__ void sts_b(const float4* v, char* hi, char* lo, int tid) {
    const int r  = tid >> 1;
    const int s0 = (tid & 1) << 3;
    #pragma unroll
    for (int i = 0; i < 8; ++i)
        split_store(hi, lo, swz((uint32_t)(r * 128 + (s0 + i) * 8)), v[i]);
}

// MODE 0: h1 = gather(x) @ w1^T  -> g_h1 (f32)
// MODE 1: h3 = gather(x) @ w3^T  -> act = silu(h1)*h3 -> g_acthi/lo (bf16 split)
// MODE 2: eout = act @ w2^T      -> g_eout (f32)
template<int MODE>
__global__ __launch_bounds__(128, 2)
void moe_gemm_mma(const float* __restrict__ W) {
    constexpr int KD  = (MODE == 2) ? FDIM : HDIM;
    constexpr int ND  = (MODE == 2) ? HDIM : FDIM;
    constexpr int NCH = KD / 64;

    extern __shared__ char smem[];
    const int e   = blockIdx.z;
    const int cnt = g_counts[e];
    const int m0  = blockIdx.y * 128;
    if (m0 >= cnt) return;
    const int n0   = blockIdx.x * 64;
    const int tid  = threadIdx.x;
    const int lane = tid & 31;
    const int wm   = tid >> 5;          // 0..3 (M); single N-warp column

    int* s_row = reinterpret_cast<int*>(smem + 2 * BUF_SZ);
    {
        int m  = m0 + tid;
        int cl = (m < cnt) ? m : (cnt - 1);
        s_row[tid] = (MODE < 2) ? g_tok[e * TOKENS + cl] : (e * TOKENS + cl);
    }
    __syncthreads();

    const uint32_t sb = smem_u32(smem);
    const __nv_bfloat16* Ahs = (MODE < 2) ? g_xhi : g_acthi;
    const __nv_bfloat16* Als = (MODE < 2) ? g_xlo : g_actlo;
    const float* Wb = W + (size_t)e * ((size_t)ND * KD) + (size_t)n0 * KD;

    float acc[2][8][4];
    #pragma unroll
    for (int i = 0; i < 2; ++i)
        #pragma unroll
        for (int j = 0; j < 8; ++j)
            #pragma unroll
            for (int q = 0; q < 4; ++q) acc[i][j][q] = 0.f;

    const int ar  = wm * 32 + (lane & 15);
    const int bnr = (lane & 7) + ((lane >> 4) << 3);   // B rows 0..63

    // ---- prologue: stage chunk 0 into buf 0 ----
    load_a_cp(Ahs, Als, s_row, KD, 0, sb + T_AHI, sb + T_ALO, tid);
    cp_commit();
    {
        float4 bv[8];
        ldg_b(Wb, KD, 0, tid, bv);
        sts_b(bv, smem + T_BHI, smem + T_BLO, tid);
    }
    cp_wait0();
    __syncthreads();

    for (int ci = 0; ci < NCH; ++ci) {
        const bool pf = (ci + 1 < NCH);
        char*    nb  = smem + ((ci + 1) & 1) * BUF_SZ;
        uint32_t nbb = sb   + ((ci + 1) & 1) * BUF_SZ;

        float4 bv[8];
        if (pf) {
            // issue next chunk's loads before MMAs: cp.async for A (no regs),
            // LDG into regs for B (converted after the MMA block)
            load_a_cp(Ahs, Als, s_row, KD, (ci + 1) * 64, nbb + T_AHI, nbb + T_ALO, tid);
            cp_commit();
            ldg_b(Wb, KD, (ci + 1) * 64, tid, bv);
        }

        // ---- MMA block on current buffer (term-outer) ----
        const uint32_t bb = sb + (ci & 1) * BUF_SZ;
        #pragma unroll
        for (int kk = 0; kk < 4; ++kk) {
            const uint32_t akoff = (uint32_t)(kk * 32 + ((lane >> 4) << 4));
            const uint32_t bkoff = (uint32_t)(kk * 32 + (((lane >> 3) & 1) << 4));

            uint32_t ah[2][4], al[2][4], bh[8][2], bl[8][2];
            #pragma unroll
            for (int i = 0; i < 2; ++i) {
                uint32_t o = swz((uint32_t)((ar + i * 16) * 128) + akoff);
                ldsm4(ah[i], bb + T_AHI + o);
                ldsm4(al[i], bb + T_ALO + o);
            }
            #pragma unroll
            for (int j = 0; j < 4; ++j) {
                uint32_t o = swz((uint32_t)((bnr + j * 16) * 128) + bkoff);
                uint32_t t[4];
                ldsm4(t, bb + T_BHI + o);
                bh[2*j][0]   = t[0]; bh[2*j][1]   = t[1];
                bh[2*j+1][0] = t[2]; bh[2*j+1][1] = t[3];
                ldsm4(t, bb + T_BLO + o);
                bl[2*j][0]   = t[0]; bl[2*j][1]   = t[1];
                bl[2*j+1][0] = t[2]; bl[2*j+1][1] = t[3];
            }
            // term-outer: 16 independent accs between same-acc reuse
            #pragma unroll
            for (int i = 0; i < 2; ++i)
                #pragma unroll
                for (int j = 0; j < 8; ++j) mma16816(acc[i][j], ah[i], bh[j]);
            #pragma unroll
            for (int i = 0; i < 2; ++i)
                #pragma unroll
                for (int j = 0; j < 8; ++j) mma16816(acc[i][j], al[i], bh[j]);
            #pragma unroll
            for (int i = 0; i < 2; ++i)
                #pragma unroll
                for (int j = 0; j < 8; ++j) mma16816(acc[i][j], ah[i], bl[j]);
        }

        if (pf) {
            sts_b(bv, nb + T_BHI, nb + T_BLO, tid);  // convert late
            cp_wait0();                               // drain A cp.async
        }
        __syncthreads();
    }

    // ---- epilogue: c-frag (lane>>2 = row-in-8, (lane&3)*2 = col pair) ----
    const int g   = lane >> 2;
    const int tc2 = (lane & 3) * 2;
    #pragma unroll
    for (int i = 0; i < 2; ++i) {
        #pragma unroll
        for (int j = 0; j < 8; ++j) {
            #pragma unroll
            for (int h = 0; h < 2; ++h) {
                const int m = m0 + wm * 32 + i * 16 + g + h * 8;
                if (m >= cnt) continue;
                const size_t slot = (size_t)e * TOKENS + m;
                const int col = n0 + j * 8 + tc2;
                const float v0 = acc[i][j][2 * h], v1 = acc[i][j][2 * h + 1];
                if (MODE == 0) {
                    *reinterpret_cast<float2*>(g_h1 + slot * FDIM + col) = make_float2(v0, v1);
                } else if (MODE == 1) {
                    float2 hv = *reinterpret_cast<const float2*>(g_h1 + slot * FDIM + col);
                    float a0 = (hv.x / (1.f + __expf(-hv.x))) * v0;
                    float a1 = (hv.y / (1.f + __expf(-hv.y))) * v1;
                    __nv_bfloat16 h0 = __float2bfloat16(a0), h1b = __float2bfloat16(a1);
                    __nv_bfloat16 l0 = __float2bfloat16(a0 - __bfloat162float(h0));
                    __nv_bfloat16 l1 = __float2bfloat16(a1 - __bfloat162float(h1b));
                    *reinterpret_cast<uint32_t*>(g_acthi + slot * FDIM + col) = pack_bf2(h0, h1b);
                    *reinterpret_cast<uint32_t*>(g_actlo + slot * FDIM + col) = pack_bf2(l0, l1);
                } else {
                    *reinterpret_cast<float2*>(g_eout + slot * HDIM + col) = make_float2(v0, v1);
                }
            }
        }
    }
}

// ---------------------------------------------------------------------------
extern "C" void kernel_launch(void* const* d_in, const int* in_sizes, int n_in,
                              void* d_out, int out_size) {
    const float* x  = (const float*)d_in[0];
    const float* gw = (const float*)d_in[1];
    const float* w1 = (const float*)d_in[2];
    const float* w2 = (const float*)d_in[3];
    const float* w3 = (const float*)d_in[4];
    float* y = (float*)d_out;

    cudaFuncSetAttribute(moe_gemm_mma<0>, cudaFuncAttributeMaxDynamicSharedMemorySize, SMEM_BYTES);
    cudaFuncSetAttribute(moe_gemm_mma<1>, cudaFuncAttributeMaxDynamicSharedMemorySize, SMEM_BYTES);
    cudaFuncSetAttribute(moe_gemm_mma<2>, cudaFuncAttributeMaxDynamicSharedMemorySize, SMEM_BYTES);

    zero_counts_kernel<<<1, 32>>>();
    router_kernel<<<TOKENS, 256>>>(x, gw);
    xsplit_kernel<<<(TOKENS * HDIM + 255) / 256, 256>>>(x);

    dim3 blk(128);
    moe_gemm_mma<0><<<dim3(FDIM / 64, 4, NUM_E), blk, SMEM_BYTES>>>(w1);
    moe_gemm_mma<1><<<dim3(FDIM / 64, 4, NUM_E), blk, SMEM_BYTES>>>(w3);
    moe_gemm_mma<2><<<dim3(HDIM / 64, 4, NUM_E), blk, SMEM_BYTES>>>(w2);

    combine_kernel<<<(TOKENS * HDIM + 255) / 256, 256>>>(y);
}

// round 12
// speedup vs baseline: 1.2420x; 1.2420x over previous
#include <cuda_runtime.h>
#include <cuda_bf16.h>
#include <cstdint>

// ---------------------------------------------------------------------------
// PhimoeSparseMoeBlock: top-2 MoE with SwiGLU experts.
//   H=4096, F=6400, E=8, K=2, T=512.
// GEMMs on the tensor pipe via mma.sync (HMMA) bf16 with a 3-term fp32->bf16
// split:  D = Ahi*Bhi + Alo*Bhi + Ahi*Blo   (fp32 accum).
// R12: warp tile 64x64 (85 B/MMA smem ratio, -33% vs R8), CTA 128x128 with
// 4 warps, K-chunk 32 with hi|lo interleaved in one 128B SW128 row =>
// 32KB/buffer, 2 CTAs/SM with independent barriers. grid.x unchanged (A
// traffic same as R8 — R11's regression came from doubling it).
// ---------------------------------------------------------------------------

#define NUM_E   8
#define TOKENS  512
#define HDIM    4096
#define FDIM    6400

// ---- scratch (device globals; no runtime allocation allowed) ----
__device__ int   g_counts[NUM_E];
__device__ int   g_tok [NUM_E * TOKENS];
__device__ int   g_slot[TOKENS * 2];
__device__ float g_wtok[TOKENS * 2];
__device__ float g_h1  [NUM_E * TOKENS * FDIM];           // 104.9 MB f32
__device__ float g_eout[NUM_E * TOKENS * HDIM];           //  67.1 MB f32
__device__ __nv_bfloat16 g_xhi  [TOKENS * HDIM];          // pre-split x
__device__ __nv_bfloat16 g_xlo  [TOKENS * HDIM];
__device__ __nv_bfloat16 g_acthi[NUM_E * TOKENS * FDIM];  // split act (52.4 MB)
__device__ __nv_bfloat16 g_actlo[NUM_E * TOKENS * FDIM];

// =========================== helpers =======================================
__device__ __forceinline__ uint32_t smem_u32(const void* p) {
    uint32_t a;
    asm("{ .reg .u64 t; cvta.to.shared.u64 t, %1; cvt.u32.u64 %0, t; }"
        : "=r"(a) : "l"(p));
    return a;
}
__device__ __forceinline__ uint32_t swz(uint32_t o) { return o ^ ((o >> 3) & 0x70); }

__device__ __forceinline__ uint32_t pack_bf2(__nv_bfloat16 a, __nv_bfloat16 b) {
    return ((uint32_t)__bfloat16_as_ushort(b) << 16) | (uint32_t)__bfloat16_as_ushort(a);
}

__device__ __forceinline__ void ldsm4(uint32_t* r, uint32_t addr) {
    asm volatile("ldmatrix.sync.aligned.m8n8.x4.shared.b16 {%0,%1,%2,%3}, [%4];"
                 : "=r"(r[0]), "=r"(r[1]), "=r"(r[2]), "=r"(r[3]) : "r"(addr));
}
__device__ __forceinline__ void mma16816(float* c, const uint32_t* a, const uint32_t* b) {
    asm volatile(
        "mma.sync.aligned.m16n8k16.row.col.f32.bf16.bf16.f32 "
        "{%0,%1,%2,%3}, {%4,%5,%6,%7}, {%8,%9}, {%0,%1,%2,%3};"
        : "+f"(c[0]), "+f"(c[1]), "+f"(c[2]), "+f"(c[3])
        : "r"(a[0]), "r"(a[1]), "r"(a[2]), "r"(a[3]), "r"(b[0]), "r"(b[1]));
}
__device__ __forceinline__ void cp_async8(uint32_t dst, const void* src) {
    asm volatile("cp.async.ca.shared.global [%0], [%1], 8;" :: "r"(dst), "l"(src));
}
__device__ __forceinline__ void cp_commit() {
    asm volatile("cp.async.commit_group;" ::: "memory");
}
__device__ __forceinline__ void cp_wait0() {
    asm volatile("cp.async.wait_group 0;" ::: "memory");
}

// ========================= router / combine / split ========================
__global__ void zero_counts_kernel() {
    if (threadIdx.x < NUM_E) g_counts[threadIdx.x] = 0;
}

__global__ void router_kernel(const float* __restrict__ x,
                              const float* __restrict__ gw) {
    const int t    = blockIdx.x;
    const int e    = threadIdx.x >> 5;
    const int lane = threadIdx.x & 31;

    const float* xr = x  + (size_t)t * HDIM;
    const float* gr = gw + (size_t)e * HDIM;

    float s = 0.f;
    for (int h = lane * 4; h < HDIM; h += 128) {
        float4 xv = *reinterpret_cast<const float4*>(xr + h);
        float4 gv = *reinterpret_cast<const float4*>(gr + h);
        s += xv.x * gv.x + xv.y * gv.y + xv.z * gv.z + xv.w * gv.w;
    }
    #pragma unroll
    for (int off = 16; off; off >>= 1) s += __shfl_xor_sync(0xffffffffu, s, off);

    __shared__ float logits[NUM_E];
    if (lane == 0) logits[e] = s;
    __syncthreads();

    if (threadIdx.x == 0) {
        float mx = logits[0];
        #pragma unroll
        for (int i = 1; i < NUM_E; ++i) mx = fmaxf(mx, logits[i]);
        float p[NUM_E]; float sum = 0.f;
        #pragma unroll
        for (int i = 0; i < NUM_E; ++i) { p[i] = expf(logits[i] - mx); sum += p[i]; }
        #pragma unroll
        for (int i = 0; i < NUM_E; ++i) p[i] /= sum;

        int i0 = 0;
        #pragma unroll
        for (int i = 1; i < NUM_E; ++i) if (p[i] > p[i0]) i0 = i;
        int i1 = (i0 == 0) ? 1 : 0;
        #pragma unroll
        for (int i = 0; i < NUM_E; ++i) if (i != i0 && p[i] > p[i1]) i1 = i;

        float denom = p[i0] + p[i1];
        int pos0 = atomicAdd(&g_counts[i0], 1);
        g_tok[i0 * TOKENS + pos0] = t;
        g_slot[t * 2 + 0] = i0 * TOKENS + pos0;
        g_wtok[t * 2 + 0] = p[i0] / denom;

        int pos1 = atomicAdd(&g_counts[i1], 1);
        g_tok[i1 * TOKENS + pos1] = t;
        g_slot[t * 2 + 1] = i1 * TOKENS + pos1;
        g_wtok[t * 2 + 1] = p[i1] / denom;
    }
}

__global__ void xsplit_kernel(const float* __restrict__ x) {
    int i = blockIdx.x * blockDim.x + threadIdx.x;
    if (i >= TOKENS * HDIM) return;
    float v = x[i];
    __nv_bfloat16 h = __float2bfloat16(v);
    g_xhi[i] = h;
    g_xlo[i] = __float2bfloat16(v - __bfloat162float(h));
}

__global__ void combine_kernel(float* __restrict__ y) {
    int idx = blockIdx.x * blockDim.x + threadIdx.x;
    if (idx >= TOKENS * HDIM) return;
    int t = idx >> 12;
    int h = idx & (HDIM - 1);
    int   s0 = g_slot[t * 2 + 0], s1 = g_slot[t * 2 + 1];
    float w0 = g_wtok[t * 2 + 0], w1 = g_wtok[t * 2 + 1];
    y[idx] = w0 * g_eout[(size_t)s0 * HDIM + h] + w1 * g_eout[(size_t)s1 * HDIM + h];
}

// =========================== HMMA GEMM =====================================
// CTA tile 128(M) x 128(N), K-chunk 32, 128 threads (4 warps, warp tile 64x64).
// smem row layout (128B, SW128): [32 bf16 hi | 32 bf16 lo].
//   A tile: 128 rows x 128B = 16KB;  B tile: 128 rows x 128B = 16KB.
//   Double-buffered: 2 x 32KB = 64KB (+ s_row) => 2 CTAs/SM.
#define T_A    0
#define T_B    16384
#define BUF_SZ 32768
#define SMEM_BYTES (2 * BUF_SZ + 512)

// split one float4 -> 8B hi + 8B lo at separate smem offsets
__device__ __forceinline__ void split_store32(char* buf, uint32_t hi_off,
                                              uint32_t lo_off, float4 v) {
    __nv_bfloat16 h0 = __float2bfloat16(v.x), h1 = __float2bfloat16(v.y),
                  h2 = __float2bfloat16(v.z), h3 = __float2bfloat16(v.w);
    __nv_bfloat16 l0 = __float2bfloat16(v.x - __bfloat162float(h0));
    __nv_bfloat16 l1 = __float2bfloat16(v.y - __bfloat162float(h1));
    __nv_bfloat16 l2 = __float2bfloat16(v.z - __bfloat162float(h2));
    __nv_bfloat16 l3 = __float2bfloat16(v.w - __bfloat162float(h3));
    *reinterpret_cast<uint2*>(buf + hi_off) = make_uint2(pack_bf2(h0, h1), pack_bf2(h2, h3));
    *reinterpret_cast<uint2*>(buf + lo_off) = make_uint2(pack_bf2(l0, l1), pack_bf2(l2, l3));
}

// A (pre-split bf16): 128 gathered rows x 32 cols -> hi|lo halves of 128B rows.
// 128 threads: tid -> r0 = tid>>3 (16 rows each), c = tid&7 (8B segment).
__device__ __forceinline__ void load_a_cp(
    const __nv_bfloat16* __restrict__ hs, const __nv_bfloat16* __restrict__ ls,
    const int* __restrict__ s_row, int ld, int kbase, uint32_t dst, int tid)
{
    const int r0 = tid >> 3;            // 0..15
    const int c  = tid & 7;             // 8B (4 bf16) segment within 64B half
    #pragma unroll
    for (int i = 0; i < 8; ++i) {
        int r = r0 + (i << 4);
        size_t off = (size_t)s_row[r] * ld + kbase + c * 4;
        cp_async8(dst + swz((uint32_t)(r * 128 + c * 8)), hs + off);
        cp_async8(dst + swz((uint32_t)(r * 128 + 64 + c * 8)), ls + off);
    }
}

// B (fp32 weights): 128 rows x 32 cols per chunk. LDG early into regs
// (coalesced: 8 consecutive threads cover one row's 128B), convert late.
__device__ __forceinline__ void ldg_b(const float* __restrict__ base, int ld,
                                      int kbase, int tid, float4* v) {
    #pragma unroll
    for (int i = 0; i < 8; ++i) {
        int f = (i << 7) + tid;          // float4 index 0..1023
        int r = f >> 3, s = f & 7;
        v[i] = *reinterpret_cast<const float4*>(base + (size_t)r * ld + kbase + s * 4);
    }
}
__device__ __forceinline__ void sts_b(const float4* v, char* buf, int tid) {
    #pragma unroll
    for (int i = 0; i < 8; ++i) {
        int f = (i << 7) + tid;
        int r = f >> 3, s = f & 7;
        split_store32(buf, swz((uint32_t)(r * 128 + s * 8)),
                           swz((uint32_t)(r * 128 + 64 + s * 8)), v[i]);
    }
}

// MODE 0: h1 = gather(x) @ w1^T  -> g_h1 (f32)
// MODE 1: h3 = gather(x) @ w3^T  -> act = silu(h1)*h3 -> g_acthi/lo (bf16 split)
// MODE 2: eout = act @ w2^T      -> g_eout (f32)
template<int MODE>
__global__ __launch_bounds__(128, 2)
void moe_gemm_mma(const float* __restrict__ W) {
    constexpr int KD  = (MODE == 2) ? FDIM : HDIM;
    constexpr int ND  = (MODE == 2) ? HDIM : FDIM;
    constexpr int NCH = KD / 32;

    extern __shared__ char smem[];
    const int e   = blockIdx.z;
    const int cnt = g_counts[e];
    const int m0  = blockIdx.y * 128;
    if (m0 >= cnt) return;
    const int n0   = blockIdx.x * 128;
    const int tid  = threadIdx.x;
    const int lane = tid & 31;
    const int wm   = (tid >> 5) >> 1;   // 0..1 (M)
    const int wn   = (tid >> 5) & 1;    // 0..1 (N)

    int* s_row = reinterpret_cast<int*>(smem + 2 * BUF_SZ);
    {
        int m  = m0 + tid;
        int cl = (m < cnt) ? m : (cnt - 1);
        s_row[tid] = (MODE < 2) ? g_tok[e * TOKENS + cl] : (e * TOKENS + cl);
    }
    __syncthreads();

    const uint32_t sb = smem_u32(smem);
    const __nv_bfloat16* Ahs = (MODE < 2) ? g_xhi : g_acthi;
    const __nv_bfloat16* Als = (MODE < 2) ? g_xlo : g_actlo;
    const float* Wb = W + (size_t)e * ((size_t)ND * KD) + (size_t)n0 * KD;

    float acc[4][8][4];
    #pragma unroll
    for (int i = 0; i < 4; ++i)
        #pragma unroll
        for (int j = 0; j < 8; ++j)
            #pragma unroll
            for (int q = 0; q < 4; ++q) acc[i][j][q] = 0.f;

    const int ar  = wm * 64 + (lane & 15);               // A rows (4 x16 groups)
    const int bnr = wn * 64 + (lane & 7) + ((lane >> 4) << 3);  // B rows (4 x16)

    // ---- prologue: stage chunk 0 into buf 0 ----
    load_a_cp(Ahs, Als, s_row, KD, 0, sb + T_A, tid);
    cp_commit();
    {
        float4 bv[8];
        ldg_b(Wb, KD, 0, tid, bv);
        sts_b(bv, smem + T_B, tid);
    }
    cp_wait0();
    __syncthreads();

    for (int ci = 0; ci < NCH; ++ci) {
        const bool pf = (ci + 1 < NCH);
        char*    nb  = smem + ((ci + 1) & 1) * BUF_SZ;
        uint32_t nbb = sb   + ((ci + 1) & 1) * BUF_SZ;

        float4 bv[8];
        if (pf) {
            load_a_cp(Ahs, Als, s_row, KD, (ci + 1) * 32, nbb + T_A, tid);
            cp_commit();
            ldg_b(Wb, KD, (ci + 1) * 32, tid, bv);
        }

        // ---- MMA block on current buffer (kk = 0,1; term-outer) ----
        const uint32_t bb = sb + (ci & 1) * BUF_SZ;
        #pragma unroll
        for (int kk = 0; kk < 2; ++kk) {
            const uint32_t akoff = (uint32_t)(kk * 32 + ((lane >> 4) << 4));
            const uint32_t bkoff = (uint32_t)(kk * 32 + (((lane >> 3) & 1) << 4));

            uint32_t ah[4][4], al[4][4], bh[8][2], bl[8][2];
            #pragma unroll
            for (int i = 0; i < 4; ++i) {
                uint32_t ro = (uint32_t)((ar + i * 16) * 128);
                ldsm4(ah[i], bb + T_A + swz(ro + akoff));
                ldsm4(al[i], bb + T_A + swz(ro + 64 + akoff));
            }
            #pragma unroll
            for (int j = 0; j < 4; ++j) {
                uint32_t ro = (uint32_t)((bnr + j * 16) * 128);
                uint32_t t[4];
                ldsm4(t, bb + T_B + swz(ro + bkoff));
                bh[2*j][0]   = t[0]; bh[2*j][1]   = t[1];
                bh[2*j+1][0] = t[2]; bh[2*j+1][1] = t[3];
                ldsm4(t, bb + T_B + swz(ro + 64 + bkoff));
                bl[2*j][0]   = t[0]; bl[2*j][1]   = t[1];
                bl[2*j+1][0] = t[2]; bl[2*j+1][1] = t[3];
            }
            // term-outer: 32 independent accs between same-acc reuse
            #pragma unroll
            for (int i = 0; i < 4; ++i)
                #pragma unroll
                for (int j = 0; j < 8; ++j) mma16816(acc[i][j], ah[i], bh[j]);
            #pragma unroll
            for (int i = 0; i < 4; ++i)
                #pragma unroll
                for (int j = 0; j < 8; ++j) mma16816(acc[i][j], al[i], bh[j]);
            #pragma unroll
            for (int i = 0; i < 4; ++i)
                #pragma unroll
                for (int j = 0; j < 8; ++j) mma16816(acc[i][j], ah[i], bl[j]);
        }

        if (pf) {
            sts_b(bv, nb + T_B, tid);   // convert late
            cp_wait0();                 // drain A cp.async
        }
        __syncthreads();
    }

    // ---- epilogue: c-frag (lane>>2 = row-in-8, (lane&3)*2 = col pair) ----
    const int g   = lane >> 2;
    const int tc2 = (lane & 3) * 2;
    #pragma unroll
    for (int i = 0; i < 4; ++i) {
        #pragma unroll
        for (int j = 0; j < 8; ++j) {
            #pragma unroll
            for (int h = 0; h < 2; ++h) {
                const int m = m0 + wm * 64 + i * 16 + g + h * 8;
                if (m >= cnt) continue;
                const size_t slot = (size_t)e * TOKENS + m;
                const int col = n0 + wn * 64 + j * 8 + tc2;
                const float v0 = acc[i][j][2 * h], v1 = acc[i][j][2 * h + 1];
                if (MODE == 0) {
                    *reinterpret_cast<float2*>(g_h1 + slot * FDIM + col) = make_float2(v0, v1);
                } else if (MODE == 1) {
                    float2 hv = *reinterpret_cast<const float2*>(g_h1 + slot * FDIM + col);
                    float a0 = (hv.x / (1.f + __expf(-hv.x))) * v0;
                    float a1 = (hv.y / (1.f + __expf(-hv.y))) * v1;
                    __nv_bfloat16 h0 = __float2bfloat16(a0), h1b = __float2bfloat16(a1);
                    __nv_bfloat16 l0 = __float2bfloat16(a0 - __bfloat162float(h0));
                    __nv_bfloat16 l1 = __float2bfloat16(a1 - __bfloat162float(h1b));
                    *reinterpret_cast<uint32_t*>(g_acthi + slot * FDIM + col) = pack_bf2(h0, h1b);
                    *reinterpret_cast<uint32_t*>(g_actlo + slot * FDIM + col) = pack_bf2(l0, l1);
                } else {
                    *reinterpret_cast<float2*>(g_eout + slot * HDIM + col) = make_float2(v0, v1);
                }
            }
        }
    }
}

// ---------------------------------------------------------------------------
extern "C" void kernel_launch(void* const* d_in, const int* in_sizes, int n_in,
                              void* d_out, int out_size) {
    const float* x  = (const float*)d_in[0];
    const float* gw = (const float*)d_in[1];
    const float* w1 = (const float*)d_in[2];
    const float* w2 = (const float*)d_in[3];
    const float* w3 = (const float*)d_in[4];
    float* y = (float*)d_out;

    cudaFuncSetAttribute(moe_gemm_mma<0>, cudaFuncAttributeMaxDynamicSharedMemorySize, SMEM_BYTES);
    cudaFuncSetAttribute(moe_gemm_mma<1>, cudaFuncAttributeMaxDynamicSharedMemorySize, SMEM_BYTES);
    cudaFuncSetAttribute(moe_gemm_mma<2>, cudaFuncAttributeMaxDynamicSharedMemorySize, SMEM_BYTES);

    zero_counts_kernel<<<1, 32>>>();
    router_kernel<<<TOKENS, 256>>>(x, gw);
    xsplit_kernel<<<(TOKENS * HDIM + 255) / 256, 256>>>(x);

    dim3 blk(128);
    moe_gemm_mma<0><<<dim3(FDIM / 128, 4, NUM_E), blk, SMEM_BYTES>>>(w1);
    moe_gemm_mma<1><<<dim3(FDIM / 128, 4, NUM_E), blk, SMEM_BYTES>>>(w3);
    moe_gemm_mma<2><<<dim3(HDIM / 128, 4, NUM_E), blk, SMEM_BYTES>>>(w2);

    combine_kernel<<<(TOKENS * HDIM + 255) / 256, 256>>>(y);
}

// round 13
// speedup vs baseline: 1.2445x; 1.0020x over previous
#include <cuda_runtime.h>
#include <cuda_bf16.h>
#include <cstdint>

// ---------------------------------------------------------------------------
// PhimoeSparseMoeBlock: top-2 MoE with SwiGLU experts.
//   H=4096, F=6400, E=8, K=2, T=512.
// GEMMs on the tensor pipe via mma.sync (HMMA) bf16 with a 3-term fp32->bf16
// split:  D = Ahi*Bhi + Alo*Bhi + Ahi*Blo   (fp32 accum).
// R12: warp tile 64x64 (85 B/MMA smem ratio, -33% vs R8), CTA 128x128 with
// 4 warps, K-chunk 32 with hi|lo interleaved in one 128B SW128 row =>
// 32KB/buffer, 2 CTAs/SM with independent barriers. grid.x unchanged (A
// traffic same as R8 — R11's regression came from doubling it).
// ---------------------------------------------------------------------------

#define NUM_E   8
#define TOKENS  512
#define HDIM    4096
#define FDIM    6400

// ---- scratch (device globals; no runtime allocation allowed) ----
__device__ int   g_counts[NUM_E];
__device__ int   g_tok [NUM_E * TOKENS];
__device__ int   g_slot[TOKENS * 2];
__device__ float g_wtok[TOKENS * 2];
__device__ float g_h1  [NUM_E * TOKENS * FDIM];           // 104.9 MB f32
__device__ float g_eout[NUM_E * TOKENS * HDIM];           //  67.1 MB f32
__device__ __nv_bfloat16 g_xhi  [TOKENS * HDIM];          // pre-split x
__device__ __nv_bfloat16 g_xlo  [TOKENS * HDIM];
__device__ __nv_bfloat16 g_acthi[NUM_E * TOKENS * FDIM];  // split act (52.4 MB)
__device__ __nv_bfloat16 g_actlo[NUM_E * TOKENS * FDIM];

// =========================== helpers =======================================
__device__ __forceinline__ uint32_t smem_u32(const void* p) {
    uint32_t a;
    asm("{ .reg .u64 t; cvta.to.shared.u64 t, %1; cvt.u32.u64 %0, t; }"
        : "=r"(a) : "l"(p));
    return a;
}
__device__ __forceinline__ uint32_t swz(uint32_t o) { return o ^ ((o >> 3) & 0x70); }

__device__ __forceinline__ uint32_t pack_bf2(__nv_bfloat16 a, __nv_bfloat16 b) {
    return ((uint32_t)__bfloat16_as_ushort(b) << 16) | (uint32_t)__bfloat16_as_ushort(a);
}

__device__ __forceinline__ void ldsm4(uint32_t* r, uint32_t addr) {
    asm volatile("ldmatrix.sync.aligned.m8n8.x4.shared.b16 {%0,%1,%2,%3}, [%4];"
                 : "=r"(r[0]), "=r"(r[1]), "=r"(r[2]), "=r"(r[3]) : "r"(addr));
}
__device__ __forceinline__ void mma16816(float* c, const uint32_t* a, const uint32_t* b) {
    asm volatile(
        "mma.sync.aligned.m16n8k16.row.col.f32.bf16.bf16.f32 "
        "{%0,%1,%2,%3}, {%4,%5,%6,%7}, {%8,%9}, {%0,%1,%2,%3};"
        : "+f"(c[0]), "+f"(c[1]), "+f"(c[2]), "+f"(c[3])
        : "r"(a[0]), "r"(a[1]), "r"(a[2]), "r"(a[3]), "r"(b[0]), "r"(b[1]));
}
__device__ __forceinline__ void cp_async8(uint32_t dst, const void* src) {
    asm volatile("cp.async.ca.shared.global [%0], [%1], 8;" :: "r"(dst), "l"(src));
}
__device__ __forceinline__ void cp_commit() {
    asm volatile("cp.async.commit_group;" ::: "memory");
}
__device__ __forceinline__ void cp_wait0() {
    asm volatile("cp.async.wait_group 0;" ::: "memory");
}

// ========================= router / combine / split ========================
__global__ void zero_counts_kernel() {
    if (threadIdx.x < NUM_E) g_counts[threadIdx.x] = 0;
}

__global__ void router_kernel(const float* __restrict__ x,
                              const float* __restrict__ gw) {
    const int t    = blockIdx.x;
    const int e    = threadIdx.x >> 5;
    const int lane = threadIdx.x & 31;

    const float* xr = x  + (size_t)t * HDIM;
    const float* gr = gw + (size_t)e * HDIM;

    float s = 0.f;
    for (int h = lane * 4; h < HDIM; h += 128) {
        float4 xv = *reinterpret_cast<const float4*>(xr + h);
        float4 gv = *reinterpret_cast<const float4*>(gr + h);
        s += xv.x * gv.x + xv.y * gv.y + xv.z * gv.z + xv.w * gv.w;
    }
    #pragma unroll
    for (int off = 16; off; off >>= 1) s += __shfl_xor_sync(0xffffffffu, s, off);

    __shared__ float logits[NUM_E];
    if (lane == 0) logits[e] = s;
    __syncthreads();

    if (threadIdx.x == 0) {
        float mx = logits[0];
        #pragma unroll
        for (int i = 1; i < NUM_E; ++i) mx = fmaxf(mx, logits[i]);
        float p[NUM_E]; float sum = 0.f;
        #pragma unroll
        for (int i = 0; i < NUM_E; ++i) { p[i] = expf(logits[i] - mx); sum += p[i]; }
        #pragma unroll
        for (int i = 0; i < NUM_E; ++i) p[i] /= sum;

        int i0 = 0;
        #pragma unroll
        for (int i = 1; i < NUM_E; ++i) if (p[i] > p[i0]) i0 = i;
        int i1 = (i0 == 0) ? 1 : 0;
        #pragma unroll
        for (int i = 0; i < NUM_E; ++i) if (i != i0 && p[i] > p[i1]) i1 = i;

        float denom = p[i0] + p[i1];
        int pos0 = atomicAdd(&g_counts[i0], 1);
        g_tok[i0 * TOKENS + pos0] = t;
        g_slot[t * 2 + 0] = i0 * TOKENS + pos0;
        g_wtok[t * 2 + 0] = p[i0] / denom;

        int pos1 = atomicAdd(&g_counts[i1], 1);
        g_tok[i1 * TOKENS + pos1] = t;
        g_slot[t * 2 + 1] = i1 * TOKENS + pos1;
        g_wtok[t * 2 + 1] = p[i1] / denom;
    }
}

__global__ void xsplit_kernel(const float* __restrict__ x) {
    int i = blockIdx.x * blockDim.x + threadIdx.x;
    if (i >= TOKENS * HDIM) return;
    float v = x[i];
    __nv_bfloat16 h = __float2bfloat16(v);
    g_xhi[i] = h;
    g_xlo[i] = __float2bfloat16(v - __bfloat162float(h));
}

__global__ void combine_kernel(float* __restrict__ y) {
    int idx = blockIdx.x * blockDim.x + threadIdx.x;
    if (idx >= TOKENS * HDIM) return;
    int t = idx >> 12;
    int h = idx & (HDIM - 1);
    int   s0 = g_slot[t * 2 + 0], s1 = g_slot[t * 2 + 1];
    float w0 = g_wtok[t * 2 + 0], w1 = g_wtok[t * 2 + 1];
    y[idx] = w0 * g_eout[(size_t)s0 * HDIM + h] + w1 * g_eout[(size_t)s1 * HDIM + h];
}

// =========================== HMMA GEMM =====================================
// CTA tile 128(M) x 128(N), K-chunk 32, 128 threads (4 warps, warp tile 64x64).
// smem row layout (128B, SW128): [32 bf16 hi | 32 bf16 lo].
//   A tile: 128 rows x 128B = 16KB;  B tile: 128 rows x 128B = 16KB.
//   Double-buffered: 2 x 32KB = 64KB (+ s_row) => 2 CTAs/SM.
#define T_A    0
#define T_B    16384
#define BUF_SZ 32768
#define SMEM_BYTES (2 * BUF_SZ + 512)

// split one float4 -> 8B hi + 8B lo at separate smem offsets
__device__ __forceinline__ void split_store32(char* buf, uint32_t hi_off,
                                              uint32_t lo_off, float4 v) {
    __nv_bfloat16 h0 = __float2bfloat16(v.x), h1 = __float2bfloat16(v.y),
                  h2 = __float2bfloat16(v.z), h3 = __float2bfloat16(v.w);
    __nv_bfloat16 l0 = __float2bfloat16(v.x - __bfloat162float(h0));
    __nv_bfloat16 l1 = __float2bfloat16(v.y - __bfloat162float(h1));
    __nv_bfloat16 l2 = __float2bfloat16(v.z - __bfloat162float(h2));
    __nv_bfloat16 l3 = __float2bfloat16(v.w - __bfloat162float(h3));
    *reinterpret_cast<uint2*>(buf + hi_off) = make_uint2(pack_bf2(h0, h1), pack_bf2(h2, h3));
    *reinterpret_cast<uint2*>(buf + lo_off) = make_uint2(pack_bf2(l0, l1), pack_bf2(l2, l3));
}

// A (pre-split bf16): 128 gathered rows x 32 cols -> hi|lo halves of 128B rows.
// 128 threads: tid -> r0 = tid>>3 (16 rows each), c = tid&7 (8B segment).
__device__ __forceinline__ void load_a_cp(
    const __nv_bfloat16* __restrict__ hs, const __nv_bfloat16* __restrict__ ls,
    const int* __restrict__ s_row, int ld, int kbase, uint32_t dst, int tid)
{
    const int r0 = tid >> 3;            // 0..15
    const int c  = tid & 7;             // 8B (4 bf16) segment within 64B half
    #pragma unroll
    for (int i = 0; i < 8; ++i) {
        int r = r0 + (i << 4);
        size_t off = (size_t)s_row[r] * ld + kbase + c * 4;
        cp_async8(dst + swz((uint32_t)(r * 128 + c * 8)), hs + off);
        cp_async8(dst + swz((uint32_t)(r * 128 + 64 + c * 8)), ls + off);
    }
}

// B (fp32 weights): 128 rows x 32 cols per chunk. LDG early into regs
// (coalesced: 8 consecutive threads cover one row's 128B), convert late.
__device__ __forceinline__ void ldg_b(const float* __restrict__ base, int ld,
                                      int kbase, int tid, float4* v) {
    #pragma unroll
    for (int i = 0; i < 8; ++i) {
        int f = (i << 7) + tid;          // float4 index 0..1023
        int r = f >> 3, s = f & 7;
        v[i] = *reinterpret_cast<const float4*>(base + (size_t)r * ld + kbase + s * 4);
    }
}
__device__ __forceinline__ void sts_b(const float4* v, char* buf, int tid) {
    #pragma unroll
    for (int i = 0; i < 8; ++i) {
        int f = (i << 7) + tid;
        int r = f >> 3, s = f & 7;
        split_store32(buf, swz((uint32_t)(r * 128 + s * 8)),
                           swz((uint32_t)(r * 128 + 64 + s * 8)), v[i]);
    }
}

// MODE 0: h1 = gather(x) @ w1^T  -> g_h1 (f32)
// MODE 1: h3 = gather(x) @ w3^T  -> act = silu(h1)*h3 -> g_acthi/lo (bf16 split)
// MODE 2: eout = act @ w2^T      -> g_eout (f32)
template<int MODE>
__global__ __launch_bounds__(128, 2)
void moe_gemm_mma(const float* __restrict__ W) {
    constexpr int KD  = (MODE == 2) ? FDIM : HDIM;
    constexpr int ND  = (MODE == 2) ? HDIM : FDIM;
    constexpr int NCH = KD / 32;

    extern __shared__ char smem[];
    const int e   = blockIdx.z;
    const int cnt = g_counts[e];
    const int m0  = blockIdx.y * 128;
    if (m0 >= cnt) return;
    const int n0   = blockIdx.x * 128;
    const int tid  = threadIdx.x;
    const int lane = tid & 31;
    const int wm   = (tid >> 5) >> 1;   // 0..1 (M)
    const int wn   = (tid >> 5) & 1;    // 0..1 (N)

    int* s_row = reinterpret_cast<int*>(smem + 2 * BUF_SZ);
    {
        int m  = m0 + tid;
        int cl = (m < cnt) ? m : (cnt - 1);
        s_row[tid] = (MODE < 2) ? g_tok[e * TOKENS + cl] : (e * TOKENS + cl);
    }
    __syncthreads();

    const uint32_t sb = smem_u32(smem);
    const __nv_bfloat16* Ahs = (MODE < 2) ? g_xhi : g_acthi;
    const __nv_bfloat16* Als = (MODE < 2) ? g_xlo : g_actlo;
    const float* Wb = W + (size_t)e * ((size_t)ND * KD) + (size_t)n0 * KD;

    float acc[4][8][4];
    #pragma unroll
    for (int i = 0; i < 4; ++i)
        #pragma unroll
        for (int j = 0; j < 8; ++j)
            #pragma unroll
            for (int q = 0; q < 4; ++q) acc[i][j][q] = 0.f;

    const int ar  = wm * 64 + (lane & 15);               // A rows (4 x16 groups)
    const int bnr = wn * 64 + (lane & 7) + ((lane >> 4) << 3);  // B rows (4 x16)

    // ---- prologue: stage chunk 0 into buf 0 ----
    load_a_cp(Ahs, Als, s_row, KD, 0, sb + T_A, tid);
    cp_commit();
    {
        float4 bv[8];
        ldg_b(Wb, KD, 0, tid, bv);
        sts_b(bv, smem + T_B, tid);
    }
    cp_wait0();
    __syncthreads();

    for (int ci = 0; ci < NCH; ++ci) {
        const bool pf = (ci + 1 < NCH);
        char*    nb  = smem + ((ci + 1) & 1) * BUF_SZ;
        uint32_t nbb = sb   + ((ci + 1) & 1) * BUF_SZ;

        float4 bv[8];
        if (pf) {
            load_a_cp(Ahs, Als, s_row, KD, (ci + 1) * 32, nbb + T_A, tid);
            cp_commit();
            ldg_b(Wb, KD, (ci + 1) * 32, tid, bv);
        }

        // ---- MMA block on current buffer (kk = 0,1; term-outer) ----
        const uint32_t bb = sb + (ci & 1) * BUF_SZ;
        #pragma unroll
        for (int kk = 0; kk < 2; ++kk) {
            const uint32_t akoff = (uint32_t)(kk * 32 + ((lane >> 4) << 4));
            const uint32_t bkoff = (uint32_t)(kk * 32 + (((lane >> 3) & 1) << 4));

            uint32_t ah[4][4], al[4][4], bh[8][2], bl[8][2];
            #pragma unroll
            for (int i = 0; i < 4; ++i) {
                uint32_t ro = (uint32_t)((ar + i * 16) * 128);
                ldsm4(ah[i], bb + T_A + swz(ro + akoff));
                ldsm4(al[i], bb + T_A + swz(ro + 64 + akoff));
            }
            #pragma unroll
            for (int j = 0; j < 4; ++j) {
                uint32_t ro = (uint32_t)((bnr + j * 16) * 128);
                uint32_t t[4];
                ldsm4(t, bb + T_B + swz(ro + bkoff));
                bh[2*j][0]   = t[0]; bh[2*j][1]   = t[1];
                bh[2*j+1][0] = t[2]; bh[2*j+1][1] = t[3];
                ldsm4(t, bb + T_B + swz(ro + 64 + bkoff));
                bl[2*j][0]   = t[0]; bl[2*j][1]   = t[1];
                bl[2*j+1][0] = t[2]; bl[2*j+1][1] = t[3];
            }
            // term-outer: 32 independent accs between same-acc reuse
            #pragma unroll
            for (int i = 0; i < 4; ++i)
                #pragma unroll
                for (int j = 0; j < 8; ++j) mma16816(acc[i][j], ah[i], bh[j]);
            #pragma unroll
            for (int i = 0; i < 4; ++i)
                #pragma unroll
                for (int j = 0; j < 8; ++j) mma16816(acc[i][j], al[i], bh[j]);
            #pragma unroll
            for (int i = 0; i < 4; ++i)
                #pragma unroll
                for (int j = 0; j < 8; ++j) mma16816(acc[i][j], ah[i], bl[j]);
        }

        if (pf) {
            sts_b(bv, nb + T_B, tid);   // convert late
            cp_wait0();                 // drain A cp.async
        }
        __syncthreads();
    }

    // ---- epilogue: c-frag (lane>>2 = row-in-8, (lane&3)*2 = col pair) ----
    const int g   = lane >> 2;
    const int tc2 = (lane & 3) * 2;
    #pragma unroll
    for (int i = 0; i < 4; ++i) {
        #pragma unroll
        for (int j = 0; j < 8; ++j) {
            #pragma unroll
            for (int h = 0; h < 2; ++h) {
                const int m = m0 + wm * 64 + i * 16 + g + h * 8;
                if (m >= cnt) continue;
                const size_t slot = (size_t)e * TOKENS + m;
                const int col = n0 + wn * 64 + j * 8 + tc2;
                const float v0 = acc[i][j][2 * h], v1 = acc[i][j][2 * h + 1];
                if (MODE == 0) {
                    *reinterpret_cast<float2*>(g_h1 + slot * FDIM + col) = make_float2(v0, v1);
                } else if (MODE == 1) {
                    float2 hv = *reinterpret_cast<const float2*>(g_h1 + slot * FDIM + col);
                    float a0 = (hv.x / (1.f + __expf(-hv.x))) * v0;
                    float a1 = (hv.y / (1.f + __expf(-hv.y))) * v1;
                    __nv_bfloat16 h0 = __float2bfloat16(a0), h1b = __float2bfloat16(a1);
                    __nv_bfloat16 l0 = __float2bfloat16(a0 - __bfloat162float(h0));
                    __nv_bfloat16 l1 = __float2bfloat16(a1 - __bfloat162float(h1b));
                    *reinterpret_cast<uint32_t*>(g_acthi + slot * FDIM + col) = pack_bf2(h0, h1b);
                    *reinterpret_cast<uint32_t*>(g_actlo + slot * FDIM + col) = pack_bf2(l0, l1);
                } else {
                    *reinterpret_cast<float2*>(g_eout + slot * HDIM + col) = make_float2(v0, v1);
                }
            }
        }
    }
}

// ---------------------------------------------------------------------------
extern "C" void kernel_launch(void* const* d_in, const int* in_sizes, int n_in,
                              void* d_out, int out_size) {
    const float* x  = (const float*)d_in[0];
    const float* gw = (const float*)d_in[1];
    const float* w1 = (const float*)d_in[2];
    const float* w2 = (const float*)d_in[3];
    const float* w3 = (const float*)d_in[4];
    float* y = (float*)d_out;

    cudaFuncSetAttribute(moe_gemm_mma<0>, cudaFuncAttributeMaxDynamicSharedMemorySize, SMEM_BYTES);
    cudaFuncSetAttribute(moe_gemm_mma<1>, cudaFuncAttributeMaxDynamicSharedMemorySize, SMEM_BYTES);
    cudaFuncSetAttribute(moe_gemm_mma<2>, cudaFuncAttributeMaxDynamicSharedMemorySize, SMEM_BYTES);

    zero_counts_kernel<<<1, 32>>>();
    router_kernel<<<TOKENS, 256>>>(x, gw);
    xsplit_kernel<<<(TOKENS * HDIM + 255) / 256, 256>>>(x);

    dim3 blk(128);
    moe_gemm_mma<0><<<dim3(FDIM / 128, 4, NUM_E), blk, SMEM_BYTES>>>(w1);
    moe_gemm_mma<1><<<dim3(FDIM / 128, 4, NUM_E), blk, SMEM_BYTES>>>(w3);
    moe_gemm_mma<2><<<dim3(HDIM / 128, 4, NUM_E), blk, SMEM_BYTES>>>(w2);

    combine_kernel<<<(TOKENS * HDIM + 255) / 256, 256>>>(y);
}